// round 14
// baseline (speedup 1.0000x reference)
#include <cuda_runtime.h>
#include <cuda_fp16.h>
#include <math.h>
#include <stdint.h>

#define T_TOK 32768
#define CDIM  512
#define NTOT  640
#define NE    8
#define NH    16

#define BM 128
#define BN 128
#define NSTAGE 16
#define STAGE_BYTES 32768
#define NBUF 4

#define SWZ(row, kw) (((row) << 4) + ((kw) ^ ((((row) >> 1) & 3) << 2)))

// ---------------- scratch ----------------
__device__ float g_h [T_TOK * CDIM];
__device__ float g_h1[T_TOK * 128];
__device__ float g_of2[2][T_TOK][CDIM];
__device__ uint32_t g_xh[T_TOK * 256];
__device__ uint32_t g_xl[T_TOK * 256];
__device__ uint32_t g_wh[NTOT * 256];
__device__ uint32_t g_wl[NTOT * 256];
__device__ float g_sum[CDIM];
__device__ float g_sumsq[CDIM];
__device__ float g_usage[NE];
__device__ int   g_te[T_TOK * 2];
__device__ float g_tw[T_TOK * 2];

// ---------------- helpers ----------------
static __device__ __forceinline__ uint32_t pack2h(float x1, float x0) {
    uint32_t r;
    asm("cvt.rn.f16x2.f32 %0, %1, %2;" : "=r"(r) : "f"(x1), "f"(x0));
    return r;
}
static __device__ __forceinline__ void mma_f16(float* d, const uint32_t* a, uint32_t b0, uint32_t b1) {
    asm volatile("mma.sync.aligned.m16n8k16.row.col.f32.f16.f16.f32 "
        "{%0,%1,%2,%3},{%4,%5,%6,%7},{%8,%9},{%0,%1,%2,%3};"
        : "+f"(d[0]), "+f"(d[1]), "+f"(d[2]), "+f"(d[3])
        : "r"(a[0]), "r"(a[1]), "r"(a[2]), "r"(a[3]), "r"(b0), "r"(b1));
}
static __device__ __forceinline__ void ldsm4(uint32_t* r, uint32_t addr) {
    asm volatile("ldmatrix.sync.aligned.m8n8.x4.shared.b16 {%0,%1,%2,%3}, [%4];"
        : "=r"(r[0]), "=r"(r[1]), "=r"(r[2]), "=r"(r[3]) : "r"(addr));
}
static __device__ __forceinline__ uint32_t smem_u32(const void* p) {
    uint32_t a;
    asm("{ .reg .u64 t; cvta.to.shared.u64 t, %1; cvt.u32.u64 %0, t; }" : "=r"(a) : "l"(p));
    return a;
}
static __device__ __forceinline__ void cpa16(uint32_t dst, const void* src) {
    asm volatile("cp.async.cg.shared.global [%0], [%1], 16;" :: "r"(dst), "l"(src));
}
#define CPA_COMMIT() asm volatile("cp.async.commit_group;" ::: "memory")
#define CPA_WAITN(n) asm volatile("cp.async.wait_group %0;" :: "n"(n) : "memory")

// ---------------- hi/lo fp16 pre-split ----------------
__global__ __launch_bounds__(256) void k_split_x(const float* __restrict__ X) {
    int idx = blockIdx.x * 256 + threadIdx.x;
    float4 v = ((const float4*)X)[idx];
    uint32_t h0 = pack2h(v.y, v.x), h1 = pack2h(v.w, v.z);
    float2 fa = __half22float2(*(__half2*)&h0);
    float2 fb = __half22float2(*(__half2*)&h1);
    uint32_t l0 = pack2h(v.y - fa.y, v.x - fa.x);
    uint32_t l1 = pack2h(v.w - fb.y, v.z - fb.x);
    ((uint2*)g_xh)[idx] = make_uint2(h0, h1);
    ((uint2*)g_xl)[idx] = make_uint2(l0, l1);
}
// merged: blocks [0,256) handle wg1 (gate), blocks [256,384) handle w1 (experts) + zero stats
__global__ __launch_bounds__(256) void k_split_w(const float* __restrict__ W,
                                                 const float* __restrict__ w1) {
    if (blockIdx.x < 256) {
        int idx = blockIdx.x * 256 + threadIdx.x;
        float4 v = ((const float4*)W)[idx];
        float a = v.x * 64.f, b = v.y * 64.f, c = v.z * 64.f, d = v.w * 64.f;
        uint32_t h0 = pack2h(b, a), h1 = pack2h(d, c);
        float2 fa = __half22float2(*(__half2*)&h0);
        float2 fb = __half22float2(*(__half2*)&h1);
        uint32_t l0 = pack2h(b - fa.y, a - fa.x);
        uint32_t l1 = pack2h(d - fb.y, c - fb.x);
        ((uint2*)g_wh)[idx] = make_uint2(h0, h1);
        ((uint2*)g_wl)[idx] = make_uint2(l0, l1);
    } else {
        int bx = blockIdx.x - 256;
        int idx = bx * 256 + threadIdx.x;
        int r = idx >> 8, k2 = idx & 255;
        int e = r >> 4, h = r & 15;
        const float* p = w1 + ((size_t)e * CDIM + 2 * k2) * NH + h;
        float a = p[0] * 64.f, b = p[NH] * 64.f;
        uint32_t hi = pack2h(b, a);
        float2 f = __half22float2(*(__half2*)&hi);
        uint32_t lo = pack2h(b - f.y, a - f.x);
        g_wh[(512 + r) * 256 + k2] = hi;
        g_wl[(512 + r) * 256 + k2] = lo;
        if (bx < 2) {
            int c = bx * 256 + threadIdx.x;
            g_sum[c] = 0.f; g_sumsq[c] = 0.f;
            if (c < NE) g_usage[c] = 0.f;
        }
    }
}

// ---------------- GEMM v4: 512 threads, NBUF=4, single barrier per stage ----------------
__global__ __launch_bounds__(512, 1) void k_gemm_mma(const float* __restrict__ bias,
                                                     const float* __restrict__ b1f) {
    extern __shared__ uint32_t sm[];
    const int m0 = blockIdx.x * BM;
    const int n0 = blockIdx.y * BN;
    const bool is_h1 = (blockIdx.y == 4);
    const int tid = threadIdx.x;
    const int lane = tid & 31;
    const int wid = tid >> 5;                 // 0..15
    const int wm = (wid & 3) * 32;            // 4 m-warps
    const int wn = (wid >> 2) * 32;           // 4 n-warps
    const int lr = lane >> 2, lc = lane & 3;
    const uint32_t base = smem_u32(sm);

    // loader: 512 threads, each 1 chunk per part per stage
    const int ldrow = tid >> 2, ldch = tid & 3;
    const uint32_t swd = 4u * (uint32_t)SWZ(ldrow, 4 * ldch);
    const uint32_t* pxh = g_xh + (size_t)(m0 + ldrow) * 256 + ldch * 4;
    const uint32_t* pxl = g_xl + (size_t)(m0 + ldrow) * 256 + ldch * 4;
    const uint32_t* pwh = g_wh + (size_t)(n0 + ldrow) * 256 + ldch * 4;
    const uint32_t* pwl = g_wl + (size_t)(n0 + ldrow) * 256 + ldch * 4;

    // hoisted ldmatrix offsets
    const int lrow8 = (lane & 7) + 8 * ((lane >> 3) & 1);
    const int kwsel = 4 * (lane >> 4);
    uint32_t aoffs[2][2], boffs[2][2];
#pragma unroll
    for (int h = 0; h < 2; h++) {
        int kw = h * 8 + kwsel;
#pragma unroll
        for (int mt = 0; mt < 2; mt++)
            aoffs[h][mt] = 4u * (uint32_t)SWZ(wm + mt * 16 + lrow8, kw);
#pragma unroll
        for (int g = 0; g < 2; g++)
            boffs[h][g] = 4u * (uint32_t)SWZ(wn + g * 16 + lrow8, kw) + 16384u;
    }

    float acc[2][4][4];
#pragma unroll
    for (int mt = 0; mt < 2; mt++)
#pragma unroll
        for (int nt = 0; nt < 4; nt++)
#pragma unroll
            for (int q = 0; q < 4; q++) acc[mt][nt][q] = 0.f;

    // prologue: stages 0..2
#pragma unroll
    for (int s = 0; s < 3; s++) {
        uint32_t st = base + s * STAGE_BYTES;
        cpa16(st + swd,         pxh + s * 16);
        cpa16(st + 8192 + swd,  pxl + s * 16);
        cpa16(st + 16384 + swd, pwh + s * 16);
        cpa16(st + 24576 + swd, pwl + s * 16);
        CPA_COMMIT();
    }

    for (int s = 0; s < NSTAGE; s++) {
        if (s <= 13) CPA_WAITN(2);
        else if (s == 14) CPA_WAITN(1);
        else CPA_WAITN(0);
        __syncthreads();    // single barrier: stage s visible, stage s-1 consumption done

        // refill stage s+3 into buffer (s+3)%4 == (s-1)%4 (safe after barrier)
        if (s + 3 < NSTAGE) {
            int sn = s + 3;
            uint32_t st2 = base + (sn % NBUF) * STAGE_BYTES;
            cpa16(st2 + swd,         pxh + sn * 16);
            cpa16(st2 + 8192 + swd,  pxl + sn * 16);
            cpa16(st2 + 16384 + swd, pwh + sn * 16);
            cpa16(st2 + 24576 + swd, pwl + sn * 16);
            CPA_COMMIT();
        }

        uint32_t st = base + (s % NBUF) * STAGE_BYTES;
#pragma unroll
        for (int h = 0; h < 2; h++) {
            uint32_t afh[2][4], afl[2][4];
#pragma unroll
            for (int mt = 0; mt < 2; mt++) {
                ldsm4(afh[mt], st + aoffs[h][mt]);
                ldsm4(afl[mt], st + 8192 + aoffs[h][mt]);
            }
#pragma unroll
            for (int g = 0; g < 2; g++) {
                uint32_t bfh[4], bfl[4];
                ldsm4(bfh, st + boffs[h][g]);
                ldsm4(bfl, st + 8192 + boffs[h][g]);
#pragma unroll
                for (int mt = 0; mt < 2; mt++) {
                    mma_f16(acc[mt][g * 2],     afh[mt], bfh[0], bfh[2]);
                    mma_f16(acc[mt][g * 2],     afh[mt], bfl[0], bfl[2]);
                    mma_f16(acc[mt][g * 2],     afl[mt], bfh[0], bfh[2]);
                    mma_f16(acc[mt][g * 2 + 1], afh[mt], bfh[1], bfh[3]);
                    mma_f16(acc[mt][g * 2 + 1], afh[mt], bfl[1], bfl[3]);
                    mma_f16(acc[mt][g * 2 + 1], afl[mt], bfh[1], bfh[3]);
                }
            }
        }
    }

    const float inv = 0.015625f;
    if (!is_h1) {
#pragma unroll
        for (int nt = 0; nt < 4; nt++) {
            int col = n0 + wn + nt * 8 + lc * 2;
            float b0 = __ldg(bias + col), b1 = __ldg(bias + col + 1);
            float s0 = 0.f, s1 = 0.f, q0 = 0.f, q1 = 0.f;
#pragma unroll
            for (int mt = 0; mt < 2; mt++) {
                int row = m0 + wm + mt * 16 + lr;
                float v00 = acc[mt][nt][0] * inv + b0;
                float v01 = acc[mt][nt][1] * inv + b1;
                float v10 = acc[mt][nt][2] * inv + b0;
                float v11 = acc[mt][nt][3] * inv + b1;
                *(float2*)(g_h + (size_t)row * CDIM + col) = make_float2(v00, v01);
                *(float2*)(g_h + (size_t)(row + 8) * CDIM + col) = make_float2(v10, v11);
                s0 += v00 + v10; s1 += v01 + v11;
                q0 = fmaf(v00, v00, q0); q0 = fmaf(v10, v10, q0);
                q1 = fmaf(v01, v01, q1); q1 = fmaf(v11, v11, q1);
            }
#pragma unroll
            for (int off = 4; off < 32; off <<= 1) {
                s0 += __shfl_xor_sync(0xffffffffu, s0, off);
                s1 += __shfl_xor_sync(0xffffffffu, s1, off);
                q0 += __shfl_xor_sync(0xffffffffu, q0, off);
                q1 += __shfl_xor_sync(0xffffffffu, q1, off);
            }
            if (lr == 0) {
                atomicAdd(&g_sum[col], s0);
                atomicAdd(&g_sum[col + 1], s1);
                atomicAdd(&g_sumsq[col], q0);
                atomicAdd(&g_sumsq[col + 1], q1);
            }
        }
    } else {
#pragma unroll
        for (int nt = 0; nt < 4; nt++) {
            int colh = wn + nt * 8 + lc * 2;
            float b0 = __ldg(b1f + colh), b1 = __ldg(b1f + colh + 1);
#pragma unroll
            for (int mt = 0; mt < 2; mt++) {
                int row = m0 + wm + mt * 16 + lr;
                float v00 = fmaxf(acc[mt][nt][0] * inv + b0, 0.f);
                float v01 = fmaxf(acc[mt][nt][1] * inv + b1, 0.f);
                float v10 = fmaxf(acc[mt][nt][2] * inv + b0, 0.f);
                float v11 = fmaxf(acc[mt][nt][3] * inv + b1, 0.f);
                *(float2*)(g_h1 + (size_t)row * 128 + colh) = make_float2(v00, v01);
                *(float2*)(g_h1 + (size_t)(row + 8) * 128 + colh) = make_float2(v10, v11);
            }
        }
    }
}

// ---------------- routing (BN finalize fused) ----------------
__global__ __launch_bounds__(256) void k_route(const float* __restrict__ wg2,
                                               const float* __restrict__ bg2,
                                               const float* __restrict__ gamma,
                                               const float* __restrict__ beta) {
    __shared__ float w2s[NE * CDIM];
    __shared__ float scs[CDIM], shs[CDIM];
    __shared__ float s_us[NE];
    int tid = threadIdx.x;
    for (int i = tid; i < NE * CDIM; i += 256) w2s[i] = wg2[i];
    for (int i = tid; i < CDIM; i += 256) {
        float mu  = g_sum[i] * (1.f / T_TOK);
        float var = g_sumsq[i] * (1.f / T_TOK) - mu * mu;
        float rstd = rsqrtf(var + 1e-5f);
        float sc = gamma[i] * rstd;
        scs[i] = sc;
        shs[i] = beta[i] - sc * mu;
    }
    if (tid < NE) s_us[tid] = 0.f;
    __syncthreads();

    int warp = tid >> 5, lane = tid & 31;
    int t0 = blockIdx.x * 16 + warp * 2;
    int t1 = t0 + 1;
    const float* h0p = g_h + (size_t)t0 * CDIM;
    const float* h1p = g_h + (size_t)t1 * CDIM;
    float a0[NE], a1[NE];
#pragma unroll
    for (int e = 0; e < NE; e++) { a0[e] = 0.f; a1[e] = 0.f; }
#pragma unroll
    for (int i = 0; i < 16; i++) {
        int c = lane + 32 * i;
        float sc = scs[c], sh = shs[c];
        float hn0 = fmaxf(fmaf(h0p[c], sc, sh), 0.f);
        float hn1 = fmaxf(fmaf(h1p[c], sc, sh), 0.f);
#pragma unroll
        for (int e = 0; e < NE; e++) {
            float w = w2s[e * CDIM + c];
            a0[e] = fmaf(hn0, w, a0[e]);
            a1[e] = fmaf(hn1, w, a1[e]);
        }
    }
#pragma unroll
    for (int e = 0; e < NE; e++)
#pragma unroll
        for (int off = 16; off > 0; off >>= 1) {
            a0[e] += __shfl_xor_sync(0xffffffffu, a0[e], off);
            a1[e] += __shfl_xor_sync(0xffffffffu, a1[e], off);
        }
    if (lane == 0) {
#pragma unroll
        for (int tt = 0; tt < 2; tt++) {
            int t = tt ? t1 : t0;
            float* ap = tt ? a1 : a0;
            float lg[NE];
#pragma unroll
            for (int e = 0; e < NE; e++) lg[e] = ap[e] + bg2[e];
            int i1 = 0; float v1 = lg[0];
#pragma unroll
            for (int e = 1; e < NE; e++) if (lg[e] > v1) { v1 = lg[e]; i1 = e; }
            int i2 = (i1 == 0) ? 1 : 0; float v2 = lg[i2];
#pragma unroll
            for (int e = 0; e < NE; e++)
                if (e != i1 && lg[e] > v2) { v2 = lg[e]; i2 = e; }
            float ew = expf(v2 - v1);
            float invs = 1.f / (1.f + ew);
            float wa = invs, wb = ew * invs;
            g_te[t * 2] = i1; g_te[t * 2 + 1] = i2;
            g_tw[t * 2] = wa; g_tw[t * 2 + 1] = wb;
            atomicAdd(&s_us[i1], wa);
            atomicAdd(&s_us[i2], wb);
        }
    }
    __syncthreads();
    if (tid < NE) atomicAdd(&g_usage[tid], s_us[tid]);
}

// ---------------- expert v4: phase-2 only ----------------
__global__ __launch_bounds__(256, 2) void k_expert(const float* __restrict__ w2,
                                                   const float* __restrict__ b2) {
    __shared__ float hs[64 * NH];
    __shared__ float wts[256];
    __shared__ int toks[256];
    __shared__ int slots[256];
    __shared__ int s_cnt;

    int e = blockIdx.y;
    int tid = threadIdx.x;
    if (tid == 0) s_cnt = 0;

    float2 w2r[NH];
    const float* w2p = w2 + (size_t)e * NH * CDIM + 2 * tid;
#pragma unroll
    for (int h = 0; h < NH; h++) w2r[h] = *(const float2*)(w2p + h * CDIM);
    float2 b2r = *(const float2*)(b2 + e * CDIM + 2 * tid);
    __syncthreads();

    {
        int t = blockIdx.x * 256 + tid;
        int e1 = g_te[t * 2], e2 = g_te[t * 2 + 1];
        int slot = (e1 == e) ? 0 : ((e2 == e) ? 1 : -1);
        if (slot >= 0) {
            int p = atomicAdd(&s_cnt, 1);
            toks[p] = t;
            slots[p] = slot;
            wts[p] = g_tw[t * 2 + slot];
        }
    }
    __syncthreads();
    int nact = s_cnt;

    for (int bb = 0; bb < nact; bb += 64) {
        int nb = min(64, nact - bb);
        for (int idx = tid; idx < nb * NH; idx += 256) {
            int r = idx >> 4, h = idx & 15;
            hs[idx] = g_h1[(size_t)toks[bb + r] * 128 + e * NH + h];
        }
        __syncthreads();
        int tl = 0;
        for (; tl + 2 <= nb; tl += 2) {
            float4 p0 = *(float4*)(hs + tl * NH);
            float4 p1 = *(float4*)(hs + tl * NH + 4);
            float4 p2 = *(float4*)(hs + tl * NH + 8);
            float4 p3 = *(float4*)(hs + tl * NH + 12);
            float4 q0v = *(float4*)(hs + (tl + 1) * NH);
            float4 q1v = *(float4*)(hs + (tl + 1) * NH + 4);
            float4 q2v = *(float4*)(hs + (tl + 1) * NH + 8);
            float4 q3v = *(float4*)(hs + (tl + 1) * NH + 12);
            float ha[NH] = { p0.x, p0.y, p0.z, p0.w, p1.x, p1.y, p1.z, p1.w,
                             p2.x, p2.y, p2.z, p2.w, p3.x, p3.y, p3.z, p3.w };
            float hb[NH] = { q0v.x, q0v.y, q0v.z, q0v.w, q1v.x, q1v.y, q1v.z, q1v.w,
                             q2v.x, q2v.y, q2v.z, q2v.w, q3v.x, q3v.y, q3v.z, q3v.w };
            float ra0 = b2r.x, ra1 = b2r.y, rb0 = b2r.x, rb1 = b2r.y;
#pragma unroll
            for (int h = 0; h < NH; h++) {
                ra0 = fmaf(ha[h], w2r[h].x, ra0);
                ra1 = fmaf(ha[h], w2r[h].y, ra1);
                rb0 = fmaf(hb[h], w2r[h].x, rb0);
                rb1 = fmaf(hb[h], w2r[h].y, rb1);
            }
            float wa = wts[bb + tl], wb = wts[bb + tl + 1];
            *(float2*)(&g_of2[slots[bb + tl]][toks[bb + tl]][2 * tid])         = make_float2(wa * ra0, wa * ra1);
            *(float2*)(&g_of2[slots[bb + tl + 1]][toks[bb + tl + 1]][2 * tid]) = make_float2(wb * rb0, wb * rb1);
        }
        if (tl < nb) {
            float4 p0 = *(float4*)(hs + tl * NH);
            float4 p1 = *(float4*)(hs + tl * NH + 4);
            float4 p2 = *(float4*)(hs + tl * NH + 8);
            float4 p3 = *(float4*)(hs + tl * NH + 12);
            float ha[NH] = { p0.x, p0.y, p0.z, p0.w, p1.x, p1.y, p1.z, p1.w,
                             p2.x, p2.y, p2.z, p2.w, p3.x, p3.y, p3.z, p3.w };
            float r0 = b2r.x, r1 = b2r.y;
#pragma unroll
            for (int h = 0; h < NH; h++) {
                r0 = fmaf(ha[h], w2r[h].x, r0);
                r1 = fmaf(ha[h], w2r[h].y, r1);
            }
            float wt = wts[bb + tl];
            *(float2*)(&g_of2[slots[bb + tl]][toks[bb + tl]][2 * tid]) = make_float2(wt * r0, wt * r1);
        }
        __syncthreads();
    }
}

// ---------------- combine + transpose ----------------
__global__ void k_transpose(float* __restrict__ out) {
    __shared__ float tile[32][33];
    int b = blockIdx.z;
    int n0 = blockIdx.x * 32, c0 = blockIdx.y * 32;
    int tx = threadIdx.x, ty = threadIdx.y;
#pragma unroll
    for (int i = 0; i < 4; i++) {
        int t = b * 4096 + n0 + ty + i * 8;
        tile[ty + i * 8][tx] = g_of2[0][t][c0 + tx] + g_of2[1][t][c0 + tx];
    }
    __syncthreads();
#pragma unroll
    for (int i = 0; i < 4; i++) {
        int c = c0 + ty + i * 8;
        out[(size_t)(b * CDIM + c) * 4096 + n0 + tx] = tile[tx][ty + i * 8];
    }
}

// ---------------- load-balance loss ----------------
__global__ void k_lb(float* __restrict__ out, int out_size) {
    float lb = 0.f;
    for (int e = 0; e < NE; e++) {
        float u = g_usage[e] * (1.f / T_TOK);
        lb += u * u;
    }
    lb *= (float)NE;
    if (out_size > T_TOK * CDIM) out[T_TOK * CDIM] = lb;
}

// ---------------- launcher ----------------
extern "C" void kernel_launch(void* const* d_in, const int* in_sizes, int n_in,
                              void* d_out, int out_size) {
    const float* x     = (const float*)d_in[0];
    const float* wg1   = (const float*)d_in[1];
    const float* bg1   = (const float*)d_in[2];
    const float* gamma = (const float*)d_in[3];
    const float* beta  = (const float*)d_in[4];
    const float* wg2   = (const float*)d_in[5];
    const float* bg2   = (const float*)d_in[6];
    const float* w1    = (const float*)d_in[7];
    const float* b1    = (const float*)d_in[8];
    const float* w2    = (const float*)d_in[9];
    const float* b2    = (const float*)d_in[10];
    float* out = (float*)d_out;

    k_split_x<<<16384, 256>>>(x);
    k_split_w<<<384, 256>>>(wg1, w1);

    int gemm_smem = NBUF * STAGE_BYTES;   // 131072
    cudaFuncSetAttribute(k_gemm_mma, cudaFuncAttributeMaxDynamicSharedMemorySize, gemm_smem);
    k_gemm_mma<<<dim3(T_TOK / BM, NTOT / BN), 512, gemm_smem>>>(bg1, b1);

    k_route<<<2048, 256>>>(wg2, bg2, gamma, beta);

    k_expert<<<dim3(128, NE), 256>>>(w2, b2);

    k_transpose<<<dim3(128, 16, 8), dim3(32, 8)>>>(out);
    k_lb<<<1, 1>>>(out, out_size);
}

// round 15
// speedup vs baseline: 1.0703x; 1.0703x over previous
#include <cuda_runtime.h>
#include <cuda_fp16.h>
#include <math.h>
#include <stdint.h>

#define T_TOK 32768
#define CDIM  512
#define NTOT  640
#define NE    8
#define NH    16

#define BM 128
#define BN 128
#define NSTAGE 16
#define STAGE_BYTES 32768
#define NBUF 3

#define SWZ(row, kw) (((row) << 4) + ((kw) ^ ((((row) >> 1) & 3) << 2)))

// ---------------- scratch ----------------
__device__ float g_h [T_TOK * CDIM];
__device__ float g_h1[T_TOK * 128];
__device__ float g_of2[2][T_TOK][CDIM];
__device__ uint32_t g_xh[T_TOK * 256];
__device__ uint32_t g_xl[T_TOK * 256];
__device__ uint32_t g_wh[NTOT * 256];
__device__ uint32_t g_wl[NTOT * 256];
__device__ float g_sum[CDIM];
__device__ float g_sumsq[CDIM];
__device__ float g_usage[NE];
__device__ int   g_te[T_TOK * 2];
__device__ float g_tw[T_TOK * 2];

// ---------------- helpers ----------------
static __device__ __forceinline__ uint32_t pack2h(float x1, float x0) {
    uint32_t r;
    asm("cvt.rn.f16x2.f32 %0, %1, %2;" : "=r"(r) : "f"(x1), "f"(x0));
    return r;
}
static __device__ __forceinline__ void mma_f16(float* d, const uint32_t* a, uint32_t b0, uint32_t b1) {
    asm volatile("mma.sync.aligned.m16n8k16.row.col.f32.f16.f16.f32 "
        "{%0,%1,%2,%3},{%4,%5,%6,%7},{%8,%9},{%0,%1,%2,%3};"
        : "+f"(d[0]), "+f"(d[1]), "+f"(d[2]), "+f"(d[3])
        : "r"(a[0]), "r"(a[1]), "r"(a[2]), "r"(a[3]), "r"(b0), "r"(b1));
}
static __device__ __forceinline__ void ldsm4(uint32_t* r, uint32_t addr) {
    asm volatile("ldmatrix.sync.aligned.m8n8.x4.shared.b16 {%0,%1,%2,%3}, [%4];"
        : "=r"(r[0]), "=r"(r[1]), "=r"(r[2]), "=r"(r[3]) : "r"(addr));
}
static __device__ __forceinline__ uint32_t smem_u32(const void* p) {
    uint32_t a;
    asm("{ .reg .u64 t; cvta.to.shared.u64 t, %1; cvt.u32.u64 %0, t; }" : "=r"(a) : "l"(p));
    return a;
}
static __device__ __forceinline__ void cpa16(uint32_t dst, const void* src) {
    asm volatile("cp.async.cg.shared.global [%0], [%1], 16;" :: "r"(dst), "l"(src));
}
#define CPA_COMMIT() asm volatile("cp.async.commit_group;" ::: "memory")
#define CPA_WAITN(n) asm volatile("cp.async.wait_group %0;" :: "n"(n) : "memory")

// ---------------- hi/lo fp16 pre-split ----------------
__global__ __launch_bounds__(256) void k_split_x(const float* __restrict__ X) {
    int idx = blockIdx.x * 256 + threadIdx.x;
    float4 v = ((const float4*)X)[idx];
    uint32_t h0 = pack2h(v.y, v.x), h1 = pack2h(v.w, v.z);
    float2 fa = __half22float2(*(__half2*)&h0);
    float2 fb = __half22float2(*(__half2*)&h1);
    uint32_t l0 = pack2h(v.y - fa.y, v.x - fa.x);
    uint32_t l1 = pack2h(v.w - fb.y, v.z - fb.x);
    ((uint2*)g_xh)[idx] = make_uint2(h0, h1);
    ((uint2*)g_xl)[idx] = make_uint2(l0, l1);
}
// merged: blocks [0,256) handle wg1 (gate), blocks [256,384) handle w1 (experts) + zero stats
__global__ __launch_bounds__(256) void k_split_w(const float* __restrict__ W,
                                                 const float* __restrict__ w1) {
    if (blockIdx.x < 256) {
        int idx = blockIdx.x * 256 + threadIdx.x;
        float4 v = ((const float4*)W)[idx];
        float a = v.x * 64.f, b = v.y * 64.f, c = v.z * 64.f, d = v.w * 64.f;
        uint32_t h0 = pack2h(b, a), h1 = pack2h(d, c);
        float2 fa = __half22float2(*(__half2*)&h0);
        float2 fb = __half22float2(*(__half2*)&h1);
        uint32_t l0 = pack2h(b - fa.y, a - fa.x);
        uint32_t l1 = pack2h(d - fb.y, c - fb.x);
        ((uint2*)g_wh)[idx] = make_uint2(h0, h1);
        ((uint2*)g_wl)[idx] = make_uint2(l0, l1);
    } else {
        int bx = blockIdx.x - 256;
        int idx = bx * 256 + threadIdx.x;
        int r = idx >> 8, k2 = idx & 255;
        int e = r >> 4, h = r & 15;
        const float* p = w1 + ((size_t)e * CDIM + 2 * k2) * NH + h;
        float a = p[0] * 64.f, b = p[NH] * 64.f;
        uint32_t hi = pack2h(b, a);
        float2 f = __half22float2(*(__half2*)&hi);
        uint32_t lo = pack2h(b - f.y, a - f.x);
        g_wh[(512 + r) * 256 + k2] = hi;
        g_wl[(512 + r) * 256 + k2] = lo;
        if (bx < 2) {
            int c = bx * 256 + threadIdx.x;
            g_sum[c] = 0.f; g_sumsq[c] = 0.f;
            if (c < NE) g_usage[c] = 0.f;
        }
    }
}

// ---------------- GEMM (round-13 exact): 256 threads, NBUF=3, 2 CTAs/SM ----------------
__global__ __launch_bounds__(256, 2) void k_gemm_mma(const float* __restrict__ bias,
                                                     const float* __restrict__ b1f) {
    extern __shared__ uint32_t sm[];
    const int m0 = blockIdx.x * BM;
    const int n0 = blockIdx.y * BN;
    const bool is_h1 = (blockIdx.y == 4);
    const int tid = threadIdx.x;
    const int lane = tid & 31;
    const int wid = tid >> 5;
    const int wm = (wid & 3) * 32;
    const int wn = (wid >> 2) * 64;
    const int lr = lane >> 2, lc = lane & 3;
    const uint32_t base = smem_u32(sm);

    const int ldrow = tid >> 2, ldch = tid & 3;
    const uint32_t swd = 4u * (uint32_t)SWZ(ldrow, 4 * ldch);
    const uint32_t swd2 = 4u * (uint32_t)SWZ(ldrow + 64, 4 * ldch);
    const uint32_t* pxh = g_xh + (size_t)(m0 + ldrow) * 256 + ldch * 4;
    const uint32_t* pxl = g_xl + (size_t)(m0 + ldrow) * 256 + ldch * 4;
    const uint32_t* pwh = g_wh + (size_t)(n0 + ldrow) * 256 + ldch * 4;
    const uint32_t* pwl = g_wl + (size_t)(n0 + ldrow) * 256 + ldch * 4;
    const int rstep = 64 * 256;

    const int lrow8 = (lane & 7) + 8 * ((lane >> 3) & 1);
    const int kwsel = 4 * (lane >> 4);
    uint32_t aoffs[2][2], boffs[2][4];
#pragma unroll
    for (int h = 0; h < 2; h++) {
        int kw = h * 8 + kwsel;
#pragma unroll
        for (int mt = 0; mt < 2; mt++)
            aoffs[h][mt] = 4u * (uint32_t)SWZ(wm + mt * 16 + lrow8, kw);
#pragma unroll
        for (int g = 0; g < 4; g++)
            boffs[h][g] = 4u * (uint32_t)SWZ(wn + g * 16 + lrow8, kw) + 16384u;
    }

    float acc[2][8][4];
#pragma unroll
    for (int mt = 0; mt < 2; mt++)
#pragma unroll
        for (int nt = 0; nt < 8; nt++)
#pragma unroll
            for (int q = 0; q < 4; q++) acc[mt][nt][q] = 0.f;

#pragma unroll
    for (int s = 0; s < NBUF; s++) {
        uint32_t st = base + s * STAGE_BYTES;
        const uint32_t* sx = pxh + s * 16;
        cpa16(st + swd, sx);
        cpa16(st + swd2, sx + rstep);
        sx = pxl + s * 16;
        cpa16(st + 8192 + swd, sx);
        cpa16(st + 8192 + swd2, sx + rstep);
        sx = pwh + s * 16;
        cpa16(st + 16384 + swd, sx);
        cpa16(st + 16384 + swd2, sx + rstep);
        sx = pwl + s * 16;
        cpa16(st + 24576 + swd, sx);
        cpa16(st + 24576 + swd2, sx + rstep);
        CPA_COMMIT();
    }

    for (int s = 0; s < NSTAGE; s++) {
        if (s <= 13) CPA_WAITN(2);
        else if (s == 14) CPA_WAITN(1);
        else CPA_WAITN(0);
        __syncthreads();

        uint32_t st = base + (s % NBUF) * STAGE_BYTES;
#pragma unroll
        for (int h = 0; h < 2; h++) {
            uint32_t afh[2][4], afl[2][4];
#pragma unroll
            for (int mt = 0; mt < 2; mt++) {
                ldsm4(afh[mt], st + aoffs[h][mt]);
                ldsm4(afl[mt], st + 8192 + aoffs[h][mt]);
            }
#pragma unroll
            for (int g = 0; g < 4; g++) {
                uint32_t bfh[4], bfl[4];
                ldsm4(bfh, st + boffs[h][g]);
                ldsm4(bfl, st + 8192 + boffs[h][g]);
#pragma unroll
                for (int mt = 0; mt < 2; mt++) {
                    mma_f16(acc[mt][g * 2],     afh[mt], bfh[0], bfh[2]);
                    mma_f16(acc[mt][g * 2],     afh[mt], bfl[0], bfl[2]);
                    mma_f16(acc[mt][g * 2],     afl[mt], bfh[0], bfh[2]);
                    mma_f16(acc[mt][g * 2 + 1], afh[mt], bfh[1], bfh[3]);
                    mma_f16(acc[mt][g * 2 + 1], afh[mt], bfl[1], bfl[3]);
                    mma_f16(acc[mt][g * 2 + 1], afl[mt], bfh[1], bfh[3]);
                }
            }
        }
        __syncthreads();
        if (s + 3 < NSTAGE) {
            int sn = s + 3;
            uint32_t st2 = base + (sn % NBUF) * STAGE_BYTES;
            const uint32_t* sx = pxh + sn * 16;
            cpa16(st2 + swd, sx);
            cpa16(st2 + swd2, sx + rstep);
            sx = pxl + sn * 16;
            cpa16(st2 + 8192 + swd, sx);
            cpa16(st2 + 8192 + swd2, sx + rstep);
            sx = pwh + sn * 16;
            cpa16(st2 + 16384 + swd, sx);
            cpa16(st2 + 16384 + swd2, sx + rstep);
            sx = pwl + sn * 16;
            cpa16(st2 + 24576 + swd, sx);
            cpa16(st2 + 24576 + swd2, sx + rstep);
            CPA_COMMIT();
        }
    }

    const float inv = 0.015625f;
    if (!is_h1) {
#pragma unroll
        for (int nt = 0; nt < 8; nt++) {
            int col = n0 + wn + nt * 8 + lc * 2;
            float b0 = __ldg(bias + col), b1 = __ldg(bias + col + 1);
            float s0 = 0.f, s1 = 0.f, q0 = 0.f, q1 = 0.f;
#pragma unroll
            for (int mt = 0; mt < 2; mt++) {
                int row = m0 + wm + mt * 16 + lr;
                float v00 = acc[mt][nt][0] * inv + b0;
                float v01 = acc[mt][nt][1] * inv + b1;
                float v10 = acc[mt][nt][2] * inv + b0;
                float v11 = acc[mt][nt][3] * inv + b1;
                *(float2*)(g_h + (size_t)row * CDIM + col) = make_float2(v00, v01);
                *(float2*)(g_h + (size_t)(row + 8) * CDIM + col) = make_float2(v10, v11);
                s0 += v00 + v10; s1 += v01 + v11;
                q0 = fmaf(v00, v00, q0); q0 = fmaf(v10, v10, q0);
                q1 = fmaf(v01, v01, q1); q1 = fmaf(v11, v11, q1);
            }
#pragma unroll
            for (int off = 4; off < 32; off <<= 1) {
                s0 += __shfl_xor_sync(0xffffffffu, s0, off);
                s1 += __shfl_xor_sync(0xffffffffu, s1, off);
                q0 += __shfl_xor_sync(0xffffffffu, q0, off);
                q1 += __shfl_xor_sync(0xffffffffu, q1, off);
            }
            if (lr == 0) {
                atomicAdd(&g_sum[col], s0);
                atomicAdd(&g_sum[col + 1], s1);
                atomicAdd(&g_sumsq[col], q0);
                atomicAdd(&g_sumsq[col + 1], q1);
            }
        }
    } else {
#pragma unroll
        for (int nt = 0; nt < 8; nt++) {
            int colh = wn + nt * 8 + lc * 2;
            float b0 = __ldg(b1f + colh), b1 = __ldg(b1f + colh + 1);
#pragma unroll
            for (int mt = 0; mt < 2; mt++) {
                int row = m0 + wm + mt * 16 + lr;
                float v00 = fmaxf(acc[mt][nt][0] * inv + b0, 0.f);
                float v01 = fmaxf(acc[mt][nt][1] * inv + b1, 0.f);
                float v10 = fmaxf(acc[mt][nt][2] * inv + b0, 0.f);
                float v11 = fmaxf(acc[mt][nt][3] * inv + b1, 0.f);
                *(float2*)(g_h1 + (size_t)row * 128 + colh) = make_float2(v00, v01);
                *(float2*)(g_h1 + (size_t)(row + 8) * 128 + colh) = make_float2(v10, v11);
            }
        }
    }
}

// ---------------- routing (BN finalize fused) ----------------
__global__ __launch_bounds__(256) void k_route(const float* __restrict__ wg2,
                                               const float* __restrict__ bg2,
                                               const float* __restrict__ gamma,
                                               const float* __restrict__ beta) {
    __shared__ float w2s[NE * CDIM];
    __shared__ float scs[CDIM], shs[CDIM];
    __shared__ float s_us[NE];
    int tid = threadIdx.x;
    for (int i = tid; i < NE * CDIM; i += 256) w2s[i] = wg2[i];
    for (int i = tid; i < CDIM; i += 256) {
        float mu  = g_sum[i] * (1.f / T_TOK);
        float var = g_sumsq[i] * (1.f / T_TOK) - mu * mu;
        float rstd = rsqrtf(var + 1e-5f);
        float sc = gamma[i] * rstd;
        scs[i] = sc;
        shs[i] = beta[i] - sc * mu;
    }
    if (tid < NE) s_us[tid] = 0.f;
    __syncthreads();

    int warp = tid >> 5, lane = tid & 31;
    int t0 = blockIdx.x * 16 + warp * 2;
    int t1 = t0 + 1;
    const float* h0p = g_h + (size_t)t0 * CDIM;
    const float* h1p = g_h + (size_t)t1 * CDIM;
    float a0[NE], a1[NE];
#pragma unroll
    for (int e = 0; e < NE; e++) { a0[e] = 0.f; a1[e] = 0.f; }
#pragma unroll
    for (int i = 0; i < 16; i++) {
        int c = lane + 32 * i;
        float sc = scs[c], sh = shs[c];
        float hn0 = fmaxf(fmaf(h0p[c], sc, sh), 0.f);
        float hn1 = fmaxf(fmaf(h1p[c], sc, sh), 0.f);
#pragma unroll
        for (int e = 0; e < NE; e++) {
            float w = w2s[e * CDIM + c];
            a0[e] = fmaf(hn0, w, a0[e]);
            a1[e] = fmaf(hn1, w, a1[e]);
        }
    }
#pragma unroll
    for (int e = 0; e < NE; e++)
#pragma unroll
        for (int off = 16; off > 0; off >>= 1) {
            a0[e] += __shfl_xor_sync(0xffffffffu, a0[e], off);
            a1[e] += __shfl_xor_sync(0xffffffffu, a1[e], off);
        }
    if (lane == 0) {
#pragma unroll
        for (int tt = 0; tt < 2; tt++) {
            int t = tt ? t1 : t0;
            float* ap = tt ? a1 : a0;
            float lg[NE];
#pragma unroll
            for (int e = 0; e < NE; e++) lg[e] = ap[e] + bg2[e];
            int i1 = 0; float v1 = lg[0];
#pragma unroll
            for (int e = 1; e < NE; e++) if (lg[e] > v1) { v1 = lg[e]; i1 = e; }
            int i2 = (i1 == 0) ? 1 : 0; float v2 = lg[i2];
#pragma unroll
            for (int e = 0; e < NE; e++)
                if (e != i1 && lg[e] > v2) { v2 = lg[e]; i2 = e; }
            float ew = expf(v2 - v1);
            float invs = 1.f / (1.f + ew);
            float wa = invs, wb = ew * invs;
            g_te[t * 2] = i1; g_te[t * 2 + 1] = i2;
            g_tw[t * 2] = wa; g_tw[t * 2 + 1] = wb;
            atomicAdd(&s_us[i1], wa);
            atomicAdd(&s_us[i2], wb);
        }
    }
    __syncthreads();
    if (tid < NE) atomicAdd(&g_usage[tid], s_us[tid]);
}

// ---------------- expert v4: phase-2 only ----------------
__global__ __launch_bounds__(256, 2) void k_expert(const float* __restrict__ w2,
                                                   const float* __restrict__ b2) {
    __shared__ float hs[64 * NH];
    __shared__ float wts[256];
    __shared__ int toks[256];
    __shared__ int slots[256];
    __shared__ int s_cnt;

    int e = blockIdx.y;
    int tid = threadIdx.x;
    if (tid == 0) s_cnt = 0;

    float2 w2r[NH];
    const float* w2p = w2 + (size_t)e * NH * CDIM + 2 * tid;
#pragma unroll
    for (int h = 0; h < NH; h++) w2r[h] = *(const float2*)(w2p + h * CDIM);
    float2 b2r = *(const float2*)(b2 + e * CDIM + 2 * tid);
    __syncthreads();

    {
        int t = blockIdx.x * 256 + tid;
        int e1 = g_te[t * 2], e2 = g_te[t * 2 + 1];
        int slot = (e1 == e) ? 0 : ((e2 == e) ? 1 : -1);
        if (slot >= 0) {
            int p = atomicAdd(&s_cnt, 1);
            toks[p] = t;
            slots[p] = slot;
            wts[p] = g_tw[t * 2 + slot];
        }
    }
    __syncthreads();
    int nact = s_cnt;

    for (int bb = 0; bb < nact; bb += 64) {
        int nb = min(64, nact - bb);
        for (int idx = tid; idx < nb * NH; idx += 256) {
            int r = idx >> 4, h = idx & 15;
            hs[idx] = g_h1[(size_t)toks[bb + r] * 128 + e * NH + h];
        }
        __syncthreads();
        int tl = 0;
        for (; tl + 2 <= nb; tl += 2) {
            float4 p0 = *(float4*)(hs + tl * NH);
            float4 p1 = *(float4*)(hs + tl * NH + 4);
            float4 p2 = *(float4*)(hs + tl * NH + 8);
            float4 p3 = *(float4*)(hs + tl * NH + 12);
            float4 q0v = *(float4*)(hs + (tl + 1) * NH);
            float4 q1v = *(float4*)(hs + (tl + 1) * NH + 4);
            float4 q2v = *(float4*)(hs + (tl + 1) * NH + 8);
            float4 q3v = *(float4*)(hs + (tl + 1) * NH + 12);
            float ha[NH] = { p0.x, p0.y, p0.z, p0.w, p1.x, p1.y, p1.z, p1.w,
                             p2.x, p2.y, p2.z, p2.w, p3.x, p3.y, p3.z, p3.w };
            float hb[NH] = { q0v.x, q0v.y, q0v.z, q0v.w, q1v.x, q1v.y, q1v.z, q1v.w,
                             q2v.x, q2v.y, q2v.z, q2v.w, q3v.x, q3v.y, q3v.z, q3v.w };
            float ra0 = b2r.x, ra1 = b2r.y, rb0 = b2r.x, rb1 = b2r.y;
#pragma unroll
            for (int h = 0; h < NH; h++) {
                ra0 = fmaf(ha[h], w2r[h].x, ra0);
                ra1 = fmaf(ha[h], w2r[h].y, ra1);
                rb0 = fmaf(hb[h], w2r[h].x, rb0);
                rb1 = fmaf(hb[h], w2r[h].y, rb1);
            }
            float wa = wts[bb + tl], wb = wts[bb + tl + 1];
            *(float2*)(&g_of2[slots[bb + tl]][toks[bb + tl]][2 * tid])         = make_float2(wa * ra0, wa * ra1);
            *(float2*)(&g_of2[slots[bb + tl + 1]][toks[bb + tl + 1]][2 * tid]) = make_float2(wb * rb0, wb * rb1);
        }
        if (tl < nb) {
            float4 p0 = *(float4*)(hs + tl * NH);
            float4 p1 = *(float4*)(hs + tl * NH + 4);
            float4 p2 = *(float4*)(hs + tl * NH + 8);
            float4 p3 = *(float4*)(hs + tl * NH + 12);
            float ha[NH] = { p0.x, p0.y, p0.z, p0.w, p1.x, p1.y, p1.z, p1.w,
                             p2.x, p2.y, p2.z, p2.w, p3.x, p3.y, p3.z, p3.w };
            float r0 = b2r.x, r1 = b2r.y;
#pragma unroll
            for (int h = 0; h < NH; h++) {
                r0 = fmaf(ha[h], w2r[h].x, r0);
                r1 = fmaf(ha[h], w2r[h].y, r1);
            }
            float wt = wts[bb + tl];
            *(float2*)(&g_of2[slots[bb + tl]][toks[bb + tl]][2 * tid]) = make_float2(wt * r0, wt * r1);
        }
        __syncthreads();
    }
}

// ---------------- combine + transpose ----------------
__global__ void k_transpose(float* __restrict__ out) {
    __shared__ float tile[32][33];
    int b = blockIdx.z;
    int n0 = blockIdx.x * 32, c0 = blockIdx.y * 32;
    int tx = threadIdx.x, ty = threadIdx.y;
#pragma unroll
    for (int i = 0; i < 4; i++) {
        int t = b * 4096 + n0 + ty + i * 8;
        tile[ty + i * 8][tx] = g_of2[0][t][c0 + tx] + g_of2[1][t][c0 + tx];
    }
    __syncthreads();
#pragma unroll
    for (int i = 0; i < 4; i++) {
        int c = c0 + ty + i * 8;
        out[(size_t)(b * CDIM + c) * 4096 + n0 + tx] = tile[tx][ty + i * 8];
    }
}

// ---------------- load-balance loss ----------------
__global__ void k_lb(float* __restrict__ out, int out_size) {
    float lb = 0.f;
    for (int e = 0; e < NE; e++) {
        float u = g_usage[e] * (1.f / T_TOK);
        lb += u * u;
    }
    lb *= (float)NE;
    if (out_size > T_TOK * CDIM) out[T_TOK * CDIM] = lb;
}

// ---------------- launcher ----------------
extern "C" void kernel_launch(void* const* d_in, const int* in_sizes, int n_in,
                              void* d_out, int out_size) {
    const float* x     = (const float*)d_in[0];
    const float* wg1   = (const float*)d_in[1];
    const float* bg1   = (const float*)d_in[2];
    const float* gamma = (const float*)d_in[3];
    const float* beta  = (const float*)d_in[4];
    const float* wg2   = (const float*)d_in[5];
    const float* bg2   = (const float*)d_in[6];
    const float* w1    = (const float*)d_in[7];
    const float* b1    = (const float*)d_in[8];
    const float* w2    = (const float*)d_in[9];
    const float* b2    = (const float*)d_in[10];
    float* out = (float*)d_out;

    k_split_x<<<16384, 256>>>(x);
    k_split_w<<<384, 256>>>(wg1, w1);

    int gemm_smem = NBUF * STAGE_BYTES;   // 98304
    cudaFuncSetAttribute(k_gemm_mma, cudaFuncAttributeMaxDynamicSharedMemorySize, gemm_smem);
    k_gemm_mma<<<dim3(T_TOK / BM, NTOT / BN), 256, gemm_smem>>>(bg1, b1);

    k_route<<<2048, 256>>>(wg2, bg2, gamma, beta);

    k_expert<<<dim3(128, NE), 256>>>(w2, b2);

    k_transpose<<<dim3(128, 16, 8), dim3(32, 8)>>>(out);
    k_lb<<<1, 1>>>(out, out_size);
}

// round 16
// speedup vs baseline: 1.0836x; 1.0124x over previous
#include <cuda_runtime.h>
#include <cuda_fp16.h>
#include <math.h>
#include <stdint.h>

#define T_TOK 32768
#define CDIM  512
#define NTOT  640
#define NE    8
#define NH    16

#define BM 128
#define BN 128
#define NSTAGE 16
#define STAGE_BYTES 32768
#define NBUF 3

#define SWZ(row, kw) (((row) << 4) + ((kw) ^ ((((row) >> 1) & 3) << 2)))

// ---------------- scratch ----------------
__device__ float g_h [T_TOK * CDIM];
__device__ float g_h1[T_TOK * 128];
__device__ float g_of2[2][T_TOK][CDIM];
__device__ uint32_t g_xh[T_TOK * 256];
__device__ uint32_t g_xl[T_TOK * 256];
__device__ uint32_t g_wh[NTOT * 256];
__device__ uint32_t g_wl[NTOT * 256];
__device__ float g_sum[CDIM];
__device__ float g_sumsq[CDIM];
__device__ float g_usage[NE];
__device__ int   g_te[T_TOK * 2];
__device__ float g_tw[T_TOK * 2];

// ---------------- helpers ----------------
static __device__ __forceinline__ uint32_t pack2h(float x1, float x0) {
    uint32_t r;
    asm("cvt.rn.f16x2.f32 %0, %1, %2;" : "=r"(r) : "f"(x1), "f"(x0));
    return r;
}
static __device__ __forceinline__ void mma_f16(float* d, const uint32_t* a, uint32_t b0, uint32_t b1) {
    asm volatile("mma.sync.aligned.m16n8k16.row.col.f32.f16.f16.f32 "
        "{%0,%1,%2,%3},{%4,%5,%6,%7},{%8,%9},{%0,%1,%2,%3};"
        : "+f"(d[0]), "+f"(d[1]), "+f"(d[2]), "+f"(d[3])
        : "r"(a[0]), "r"(a[1]), "r"(a[2]), "r"(a[3]), "r"(b0), "r"(b1));
}
static __device__ __forceinline__ void ldsm4(uint32_t* r, uint32_t addr) {
    asm volatile("ldmatrix.sync.aligned.m8n8.x4.shared.b16 {%0,%1,%2,%3}, [%4];"
        : "=r"(r[0]), "=r"(r[1]), "=r"(r[2]), "=r"(r[3]) : "r"(addr));
}
static __device__ __forceinline__ uint32_t smem_u32(const void* p) {
    uint32_t a;
    asm("{ .reg .u64 t; cvta.to.shared.u64 t, %1; cvt.u32.u64 %0, t; }" : "=r"(a) : "l"(p));
    return a;
}
static __device__ __forceinline__ void cpa16(uint32_t dst, const void* src) {
    asm volatile("cp.async.cg.shared.global [%0], [%1], 16;" :: "r"(dst), "l"(src));
}
#define CPA_COMMIT() asm volatile("cp.async.commit_group;" ::: "memory")
#define CPA_WAITN(n) asm volatile("cp.async.wait_group %0;" :: "n"(n) : "memory")

// ---------------- hi/lo fp16 pre-split ----------------
__global__ __launch_bounds__(256) void k_split_x(const float* __restrict__ X) {
    int idx = blockIdx.x * 256 + threadIdx.x;
    float4 v = ((const float4*)X)[idx];
    uint32_t h0 = pack2h(v.y, v.x), h1 = pack2h(v.w, v.z);
    float2 fa = __half22float2(*(__half2*)&h0);
    float2 fb = __half22float2(*(__half2*)&h1);
    uint32_t l0 = pack2h(v.y - fa.y, v.x - fa.x);
    uint32_t l1 = pack2h(v.w - fb.y, v.z - fb.x);
    ((uint2*)g_xh)[idx] = make_uint2(h0, h1);
    ((uint2*)g_xl)[idx] = make_uint2(l0, l1);
}
__global__ __launch_bounds__(256) void k_split_w(const float* __restrict__ W,
                                                 const float* __restrict__ w1) {
    if (blockIdx.x < 256) {
        int idx = blockIdx.x * 256 + threadIdx.x;
        float4 v = ((const float4*)W)[idx];
        float a = v.x * 64.f, b = v.y * 64.f, c = v.z * 64.f, d = v.w * 64.f;
        uint32_t h0 = pack2h(b, a), h1 = pack2h(d, c);
        float2 fa = __half22float2(*(__half2*)&h0);
        float2 fb = __half22float2(*(__half2*)&h1);
        uint32_t l0 = pack2h(b - fa.y, a - fa.x);
        uint32_t l1 = pack2h(d - fb.y, c - fb.x);
        ((uint2*)g_wh)[idx] = make_uint2(h0, h1);
        ((uint2*)g_wl)[idx] = make_uint2(l0, l1);
    } else {
        int bx = blockIdx.x - 256;
        int idx = bx * 256 + threadIdx.x;
        int r = idx >> 8, k2 = idx & 255;
        int e = r >> 4, h = r & 15;
        const float* p = w1 + ((size_t)e * CDIM + 2 * k2) * NH + h;
        float a = p[0] * 64.f, b = p[NH] * 64.f;
        uint32_t hi = pack2h(b, a);
        float2 f = __half22float2(*(__half2*)&hi);
        uint32_t lo = pack2h(b - f.y, a - f.x);
        g_wh[(512 + r) * 256 + k2] = hi;
        g_wl[(512 + r) * 256 + k2] = lo;
        if (bx < 2) {
            int c = bx * 256 + threadIdx.x;
            g_sum[c] = 0.f; g_sumsq[c] = 0.f;
            if (c < NE) g_usage[c] = 0.f;
        }
    }
}

// ---------------- GEMM (round-13 exact): 256 threads, NBUF=3, 2 CTAs/SM ----------------
__global__ __launch_bounds__(256, 2) void k_gemm_mma(const float* __restrict__ bias,
                                                     const float* __restrict__ b1f) {
    extern __shared__ uint32_t sm[];
    const int m0 = blockIdx.x * BM;
    const int n0 = blockIdx.y * BN;
    const bool is_h1 = (blockIdx.y == 4);
    const int tid = threadIdx.x;
    const int lane = tid & 31;
    const int wid = tid >> 5;
    const int wm = (wid & 3) * 32;
    const int wn = (wid >> 2) * 64;
    const int lr = lane >> 2, lc = lane & 3;
    const uint32_t base = smem_u32(sm);

    const int ldrow = tid >> 2, ldch = tid & 3;
    const uint32_t swd = 4u * (uint32_t)SWZ(ldrow, 4 * ldch);
    const uint32_t swd2 = 4u * (uint32_t)SWZ(ldrow + 64, 4 * ldch);
    const uint32_t* pxh = g_xh + (size_t)(m0 + ldrow) * 256 + ldch * 4;
    const uint32_t* pxl = g_xl + (size_t)(m0 + ldrow) * 256 + ldch * 4;
    const uint32_t* pwh = g_wh + (size_t)(n0 + ldrow) * 256 + ldch * 4;
    const uint32_t* pwl = g_wl + (size_t)(n0 + ldrow) * 256 + ldch * 4;
    const int rstep = 64 * 256;

    const int lrow8 = (lane & 7) + 8 * ((lane >> 3) & 1);
    const int kwsel = 4 * (lane >> 4);
    uint32_t aoffs[2][2], boffs[2][4];
#pragma unroll
    for (int h = 0; h < 2; h++) {
        int kw = h * 8 + kwsel;
#pragma unroll
        for (int mt = 0; mt < 2; mt++)
            aoffs[h][mt] = 4u * (uint32_t)SWZ(wm + mt * 16 + lrow8, kw);
#pragma unroll
        for (int g = 0; g < 4; g++)
            boffs[h][g] = 4u * (uint32_t)SWZ(wn + g * 16 + lrow8, kw) + 16384u;
    }

    float acc[2][8][4];
#pragma unroll
    for (int mt = 0; mt < 2; mt++)
#pragma unroll
        for (int nt = 0; nt < 8; nt++)
#pragma unroll
            for (int q = 0; q < 4; q++) acc[mt][nt][q] = 0.f;

#pragma unroll
    for (int s = 0; s < NBUF; s++) {
        uint32_t st = base + s * STAGE_BYTES;
        const uint32_t* sx = pxh + s * 16;
        cpa16(st + swd, sx);
        cpa16(st + swd2, sx + rstep);
        sx = pxl + s * 16;
        cpa16(st + 8192 + swd, sx);
        cpa16(st + 8192 + swd2, sx + rstep);
        sx = pwh + s * 16;
        cpa16(st + 16384 + swd, sx);
        cpa16(st + 16384 + swd2, sx + rstep);
        sx = pwl + s * 16;
        cpa16(st + 24576 + swd, sx);
        cpa16(st + 24576 + swd2, sx + rstep);
        CPA_COMMIT();
    }

    for (int s = 0; s < NSTAGE; s++) {
        if (s <= 13) CPA_WAITN(2);
        else if (s == 14) CPA_WAITN(1);
        else CPA_WAITN(0);
        __syncthreads();

        uint32_t st = base + (s % NBUF) * STAGE_BYTES;
#pragma unroll
        for (int h = 0; h < 2; h++) {
            uint32_t afh[2][4], afl[2][4];
#pragma unroll
            for (int mt = 0; mt < 2; mt++) {
                ldsm4(afh[mt], st + aoffs[h][mt]);
                ldsm4(afl[mt], st + 8192 + aoffs[h][mt]);
            }
#pragma unroll
            for (int g = 0; g < 4; g++) {
                uint32_t bfh[4], bfl[4];
                ldsm4(bfh, st + boffs[h][g]);
                ldsm4(bfl, st + 8192 + boffs[h][g]);
#pragma unroll
                for (int mt = 0; mt < 2; mt++) {
                    mma_f16(acc[mt][g * 2],     afh[mt], bfh[0], bfh[2]);
                    mma_f16(acc[mt][g * 2],     afh[mt], bfl[0], bfl[2]);
                    mma_f16(acc[mt][g * 2],     afl[mt], bfh[0], bfh[2]);
                    mma_f16(acc[mt][g * 2 + 1], afh[mt], bfh[1], bfh[3]);
                    mma_f16(acc[mt][g * 2 + 1], afh[mt], bfl[1], bfl[3]);
                    mma_f16(acc[mt][g * 2 + 1], afl[mt], bfh[1], bfh[3]);
                }
            }
        }
        __syncthreads();
        if (s + 3 < NSTAGE) {
            int sn = s + 3;
            uint32_t st2 = base + (sn % NBUF) * STAGE_BYTES;
            const uint32_t* sx = pxh + sn * 16;
            cpa16(st2 + swd, sx);
            cpa16(st2 + swd2, sx + rstep);
            sx = pxl + sn * 16;
            cpa16(st2 + 8192 + swd, sx);
            cpa16(st2 + 8192 + swd2, sx + rstep);
            sx = pwh + sn * 16;
            cpa16(st2 + 16384 + swd, sx);
            cpa16(st2 + 16384 + swd2, sx + rstep);
            sx = pwl + sn * 16;
            cpa16(st2 + 24576 + swd, sx);
            cpa16(st2 + 24576 + swd2, sx + rstep);
            CPA_COMMIT();
        }
    }

    const float inv = 0.015625f;
    if (!is_h1) {
#pragma unroll
        for (int nt = 0; nt < 8; nt++) {
            int col = n0 + wn + nt * 8 + lc * 2;
            float b0 = __ldg(bias + col), b1 = __ldg(bias + col + 1);
            float s0 = 0.f, s1 = 0.f, q0 = 0.f, q1 = 0.f;
#pragma unroll
            for (int mt = 0; mt < 2; mt++) {
                int row = m0 + wm + mt * 16 + lr;
                float v00 = acc[mt][nt][0] * inv + b0;
                float v01 = acc[mt][nt][1] * inv + b1;
                float v10 = acc[mt][nt][2] * inv + b0;
                float v11 = acc[mt][nt][3] * inv + b1;
                *(float2*)(g_h + (size_t)row * CDIM + col) = make_float2(v00, v01);
                *(float2*)(g_h + (size_t)(row + 8) * CDIM + col) = make_float2(v10, v11);
                s0 += v00 + v10; s1 += v01 + v11;
                q0 = fmaf(v00, v00, q0); q0 = fmaf(v10, v10, q0);
                q1 = fmaf(v01, v01, q1); q1 = fmaf(v11, v11, q1);
            }
#pragma unroll
            for (int off = 4; off < 32; off <<= 1) {
                s0 += __shfl_xor_sync(0xffffffffu, s0, off);
                s1 += __shfl_xor_sync(0xffffffffu, s1, off);
                q0 += __shfl_xor_sync(0xffffffffu, q0, off);
                q1 += __shfl_xor_sync(0xffffffffu, q1, off);
            }
            if (lr == 0) {
                atomicAdd(&g_sum[col], s0);
                atomicAdd(&g_sum[col + 1], s1);
                atomicAdd(&g_sumsq[col], q0);
                atomicAdd(&g_sumsq[col + 1], q1);
            }
        }
    } else {
#pragma unroll
        for (int nt = 0; nt < 8; nt++) {
            int colh = wn + nt * 8 + lc * 2;
            float b0 = __ldg(b1f + colh), b1 = __ldg(b1f + colh + 1);
#pragma unroll
            for (int mt = 0; mt < 2; mt++) {
                int row = m0 + wm + mt * 16 + lr;
                float v00 = fmaxf(acc[mt][nt][0] * inv + b0, 0.f);
                float v01 = fmaxf(acc[mt][nt][1] * inv + b1, 0.f);
                float v10 = fmaxf(acc[mt][nt][2] * inv + b0, 0.f);
                float v11 = fmaxf(acc[mt][nt][3] * inv + b1, 0.f);
                *(float2*)(g_h1 + (size_t)row * 128 + colh) = make_float2(v00, v01);
                *(float2*)(g_h1 + (size_t)(row + 8) * 128 + colh) = make_float2(v10, v11);
            }
        }
    }
}

// ---------------- routing (BN fused, float2-vectorized inner loop) ----------------
__global__ __launch_bounds__(256) void k_route(const float* __restrict__ wg2,
                                               const float* __restrict__ bg2,
                                               const float* __restrict__ gamma,
                                               const float* __restrict__ beta) {
    __shared__ float w2s[NE * CDIM];
    __shared__ float scs[CDIM], shs[CDIM];
    __shared__ float s_us[NE];
    int tid = threadIdx.x;
    for (int i = tid; i < NE * CDIM; i += 256) w2s[i] = wg2[i];
    for (int i = tid; i < CDIM; i += 256) {
        float mu  = g_sum[i] * (1.f / T_TOK);
        float var = g_sumsq[i] * (1.f / T_TOK) - mu * mu;
        float rstd = rsqrtf(var + 1e-5f);
        float sc = gamma[i] * rstd;
        scs[i] = sc;
        shs[i] = beta[i] - sc * mu;
    }
    if (tid < NE) s_us[tid] = 0.f;
    __syncthreads();

    int warp = tid >> 5, lane = tid & 31;
    int t0 = blockIdx.x * 16 + warp * 2;
    int t1 = t0 + 1;
    const float* h0p = g_h + (size_t)t0 * CDIM;
    const float* h1p = g_h + (size_t)t1 * CDIM;
    float a0[NE], a1[NE];
#pragma unroll
    for (int e = 0; e < NE; e++) { a0[e] = 0.f; a1[e] = 0.f; }
#pragma unroll
    for (int i = 0; i < 8; i++) {
        int c = 2 * lane + 64 * i;      // lane owns channel pair (c, c+1)
        float2 hv0 = *(const float2*)(h0p + c);
        float2 hv1 = *(const float2*)(h1p + c);
        float2 sc2 = *(const float2*)(scs + c);
        float2 sh2 = *(const float2*)(shs + c);
        float n0x = fmaxf(fmaf(hv0.x, sc2.x, sh2.x), 0.f);
        float n0y = fmaxf(fmaf(hv0.y, sc2.y, sh2.y), 0.f);
        float n1x = fmaxf(fmaf(hv1.x, sc2.x, sh2.x), 0.f);
        float n1y = fmaxf(fmaf(hv1.y, sc2.y, sh2.y), 0.f);
#pragma unroll
        for (int e = 0; e < NE; e++) {
            float2 w = *(const float2*)(w2s + e * CDIM + c);
            a0[e] = fmaf(n0x, w.x, a0[e]); a0[e] = fmaf(n0y, w.y, a0[e]);
            a1[e] = fmaf(n1x, w.x, a1[e]); a1[e] = fmaf(n1y, w.y, a1[e]);
        }
    }
#pragma unroll
    for (int e = 0; e < NE; e++)
#pragma unroll
        for (int off = 16; off > 0; off >>= 1) {
            a0[e] += __shfl_xor_sync(0xffffffffu, a0[e], off);
            a1[e] += __shfl_xor_sync(0xffffffffu, a1[e], off);
        }
    if (lane == 0) {
#pragma unroll
        for (int tt = 0; tt < 2; tt++) {
            int t = tt ? t1 : t0;
            float* ap = tt ? a1 : a0;
            float lg[NE];
#pragma unroll
            for (int e = 0; e < NE; e++) lg[e] = ap[e] + bg2[e];
            int i1 = 0; float v1 = lg[0];
#pragma unroll
            for (int e = 1; e < NE; e++) if (lg[e] > v1) { v1 = lg[e]; i1 = e; }
            int i2 = (i1 == 0) ? 1 : 0; float v2 = lg[i2];
#pragma unroll
            for (int e = 0; e < NE; e++)
                if (e != i1 && lg[e] > v2) { v2 = lg[e]; i2 = e; }
            float ew = expf(v2 - v1);
            float invs = 1.f / (1.f + ew);
            float wa = invs, wb = ew * invs;
            g_te[t * 2] = i1; g_te[t * 2 + 1] = i2;
            g_tw[t * 2] = wa; g_tw[t * 2 + 1] = wb;
            atomicAdd(&s_us[i1], wa);
            atomicAdd(&s_us[i2], wb);
        }
    }
    __syncthreads();
    if (tid < NE) atomicAdd(&g_usage[tid], s_us[tid]);
}

// ---------------- expert v4: phase-2 only ----------------
__global__ __launch_bounds__(256, 2) void k_expert(const float* __restrict__ w2,
                                                   const float* __restrict__ b2) {
    __shared__ float hs[64 * NH];
    __shared__ float wts[256];
    __shared__ int toks[256];
    __shared__ int slots[256];
    __shared__ int s_cnt;

    int e = blockIdx.y;
    int tid = threadIdx.x;
    if (tid == 0) s_cnt = 0;

    float2 w2r[NH];
    const float* w2p = w2 + (size_t)e * NH * CDIM + 2 * tid;
#pragma unroll
    for (int h = 0; h < NH; h++) w2r[h] = *(const float2*)(w2p + h * CDIM);
    float2 b2r = *(const float2*)(b2 + e * CDIM + 2 * tid);
    __syncthreads();

    {
        int t = blockIdx.x * 256 + tid;
        int e1 = g_te[t * 2], e2 = g_te[t * 2 + 1];
        int slot = (e1 == e) ? 0 : ((e2 == e) ? 1 : -1);
        if (slot >= 0) {
            int p = atomicAdd(&s_cnt, 1);
            toks[p] = t;
            slots[p] = slot;
            wts[p] = g_tw[t * 2 + slot];
        }
    }
    __syncthreads();
    int nact = s_cnt;

    for (int bb = 0; bb < nact; bb += 64) {
        int nb = min(64, nact - bb);
        for (int idx = tid; idx < nb * NH; idx += 256) {
            int r = idx >> 4, h = idx & 15;
            hs[idx] = g_h1[(size_t)toks[bb + r] * 128 + e * NH + h];
        }
        __syncthreads();
        int tl = 0;
        for (; tl + 2 <= nb; tl += 2) {
            float4 p0 = *(float4*)(hs + tl * NH);
            float4 p1 = *(float4*)(hs + tl * NH + 4);
            float4 p2 = *(float4*)(hs + tl * NH + 8);
            float4 p3 = *(float4*)(hs + tl * NH + 12);
            float4 q0v = *(float4*)(hs + (tl + 1) * NH);
            float4 q1v = *(float4*)(hs + (tl + 1) * NH + 4);
            float4 q2v = *(float4*)(hs + (tl + 1) * NH + 8);
            float4 q3v = *(float4*)(hs + (tl + 1) * NH + 12);
            float ha[NH] = { p0.x, p0.y, p0.z, p0.w, p1.x, p1.y, p1.z, p1.w,
                             p2.x, p2.y, p2.z, p2.w, p3.x, p3.y, p3.z, p3.w };
            float hb[NH] = { q0v.x, q0v.y, q0v.z, q0v.w, q1v.x, q1v.y, q1v.z, q1v.w,
                             q2v.x, q2v.y, q2v.z, q2v.w, q3v.x, q3v.y, q3v.z, q3v.w };
            float ra0 = b2r.x, ra1 = b2r.y, rb0 = b2r.x, rb1 = b2r.y;
#pragma unroll
            for (int h = 0; h < NH; h++) {
                ra0 = fmaf(ha[h], w2r[h].x, ra0);
                ra1 = fmaf(ha[h], w2r[h].y, ra1);
                rb0 = fmaf(hb[h], w2r[h].x, rb0);
                rb1 = fmaf(hb[h], w2r[h].y, rb1);
            }
            float wa = wts[bb + tl], wb = wts[bb + tl + 1];
            *(float2*)(&g_of2[slots[bb + tl]][toks[bb + tl]][2 * tid])         = make_float2(wa * ra0, wa * ra1);
            *(float2*)(&g_of2[slots[bb + tl + 1]][toks[bb + tl + 1]][2 * tid]) = make_float2(wb * rb0, wb * rb1);
        }
        if (tl < nb) {
            float4 p0 = *(float4*)(hs + tl * NH);
            float4 p1 = *(float4*)(hs + tl * NH + 4);
            float4 p2 = *(float4*)(hs + tl * NH + 8);
            float4 p3 = *(float4*)(hs + tl * NH + 12);
            float ha[NH] = { p0.x, p0.y, p0.z, p0.w, p1.x, p1.y, p1.z, p1.w,
                             p2.x, p2.y, p2.z, p2.w, p3.x, p3.y, p3.z, p3.w };
            float r0 = b2r.x, r1 = b2r.y;
#pragma unroll
            for (int h = 0; h < NH; h++) {
                r0 = fmaf(ha[h], w2r[h].x, r0);
                r1 = fmaf(ha[h], w2r[h].y, r1);
            }
            float wt = wts[bb + tl];
            *(float2*)(&g_of2[slots[bb + tl]][toks[bb + tl]][2 * tid]) = make_float2(wt * r0, wt * r1);
        }
        __syncthreads();
    }
}

// ---------------- combine + transpose ----------------
__global__ void k_transpose(float* __restrict__ out) {
    __shared__ float tile[32][33];
    int b = blockIdx.z;
    int n0 = blockIdx.x * 32, c0 = blockIdx.y * 32;
    int tx = threadIdx.x, ty = threadIdx.y;
#pragma unroll
    for (int i = 0; i < 4; i++) {
        int t = b * 4096 + n0 + ty + i * 8;
        tile[ty + i * 8][tx] = g_of2[0][t][c0 + tx] + g_of2[1][t][c0 + tx];
    }
    __syncthreads();
#pragma unroll
    for (int i = 0; i < 4; i++) {
        int c = c0 + ty + i * 8;
        out[(size_t)(b * CDIM + c) * 4096 + n0 + tx] = tile[tx][ty + i * 8];
    }
}

// ---------------- load-balance loss ----------------
__global__ void k_lb(float* __restrict__ out, int out_size) {
    float lb = 0.f;
    for (int e = 0; e < NE; e++) {
        float u = g_usage[e] * (1.f / T_TOK);
        lb += u * u;
    }
    lb *= (float)NE;
    if (out_size > T_TOK * CDIM) out[T_TOK * CDIM] = lb;
}

// ---------------- launcher ----------------
extern "C" void kernel_launch(void* const* d_in, const int* in_sizes, int n_in,
                              void* d_out, int out_size) {
    const float* x     = (const float*)d_in[0];
    const float* wg1   = (const float*)d_in[1];
    const float* bg1   = (const float*)d_in[2];
    const float* gamma = (const float*)d_in[3];
    const float* beta  = (const float*)d_in[4];
    const float* wg2   = (const float*)d_in[5];
    const float* bg2   = (const float*)d_in[6];
    const float* w1    = (const float*)d_in[7];
    const float* b1    = (const float*)d_in[8];
    const float* w2    = (const float*)d_in[9];
    const float* b2    = (const float*)d_in[10];
    float* out = (float*)d_out;

    k_split_x<<<16384, 256>>>(x);
    k_split_w<<<384, 256>>>(wg1, w1);

    int gemm_smem = NBUF * STAGE_BYTES;
    cudaFuncSetAttribute(k_gemm_mma, cudaFuncAttributeMaxDynamicSharedMemorySize, gemm_smem);
    k_gemm_mma<<<dim3(T_TOK / BM, NTOT / BN), 256, gemm_smem>>>(bg1, b1);

    k_route<<<2048, 256>>>(wg2, bg2, gamma, beta);

    k_expert<<<dim3(128, NE), 256>>>(w2, b2);

    k_transpose<<<dim3(128, 16, 8), dim3(32, 8)>>>(out);
    k_lb<<<1, 1>>>(out, out_size);
}

// round 17
// speedup vs baseline: 1.0892x; 1.0052x over previous
#include <cuda_runtime.h>
#include <cuda_fp16.h>
#include <math.h>
#include <stdint.h>

#define T_TOK 32768
#define CDIM  512
#define NTOT  640
#define NE    8
#define NH    16

#define BM 128
#define BN 128
#define NSTAGE 16
#define STAGE_BYTES 32768
#define NBUF 3

#define SWZ(row, kw) (((row) << 4) + ((kw) ^ ((((row) >> 1) & 3) << 2)))

// ---------------- scratch ----------------
__device__ float g_h [T_TOK * CDIM];
__device__ float g_h1[T_TOK * 128];
__device__ float g_of2[2][T_TOK][CDIM];
__device__ uint32_t g_xh[T_TOK * 256];
__device__ uint32_t g_xl[T_TOK * 256];
__device__ uint32_t g_wh[NTOT * 256];
__device__ uint32_t g_wl[NTOT * 256];
__device__ float g_sum[CDIM];
__device__ float g_sumsq[CDIM];
__device__ float g_usage[NE];
__device__ int   g_te[T_TOK * 2];
__device__ float g_tw[T_TOK * 2];

// ---------------- helpers ----------------
static __device__ __forceinline__ uint32_t pack2h(float x1, float x0) {
    uint32_t r;
    asm("cvt.rn.f16x2.f32 %0, %1, %2;" : "=r"(r) : "f"(x1), "f"(x0));
    return r;
}
static __device__ __forceinline__ void mma_f16(float* d, const uint32_t* a, uint32_t b0, uint32_t b1) {
    asm volatile("mma.sync.aligned.m16n8k16.row.col.f32.f16.f16.f32 "
        "{%0,%1,%2,%3},{%4,%5,%6,%7},{%8,%9},{%0,%1,%2,%3};"
        : "+f"(d[0]), "+f"(d[1]), "+f"(d[2]), "+f"(d[3])
        : "r"(a[0]), "r"(a[1]), "r"(a[2]), "r"(a[3]), "r"(b0), "r"(b1));
}
static __device__ __forceinline__ void ldsm4(uint32_t* r, uint32_t addr) {
    asm volatile("ldmatrix.sync.aligned.m8n8.x4.shared.b16 {%0,%1,%2,%3}, [%4];"
        : "=r"(r[0]), "=r"(r[1]), "=r"(r[2]), "=r"(r[3]) : "r"(addr));
}
static __device__ __forceinline__ uint32_t smem_u32(const void* p) {
    uint32_t a;
    asm("{ .reg .u64 t; cvta.to.shared.u64 t, %1; cvt.u32.u64 %0, t; }" : "=r"(a) : "l"(p));
    return a;
}
static __device__ __forceinline__ void cpa16(uint32_t dst, const void* src) {
    asm volatile("cp.async.cg.shared.global [%0], [%1], 16;" :: "r"(dst), "l"(src));
}
#define CPA_COMMIT() asm volatile("cp.async.commit_group;" ::: "memory")
#define CPA_WAITN(n) asm volatile("cp.async.wait_group %0;" :: "n"(n) : "memory")

// ---------------- merged pre-split: X (blocks 0..16383) + W/w1 (blocks 16384..16767) ----------------
__global__ __launch_bounds__(256) void k_split(const float* __restrict__ X,
                                               const float* __restrict__ W,
                                               const float* __restrict__ w1) {
    if (blockIdx.x < 16384) {
        int idx = blockIdx.x * 256 + threadIdx.x;
        float4 v = ((const float4*)X)[idx];
        uint32_t h0 = pack2h(v.y, v.x), h1 = pack2h(v.w, v.z);
        float2 fa = __half22float2(*(__half2*)&h0);
        float2 fb = __half22float2(*(__half2*)&h1);
        uint32_t l0 = pack2h(v.y - fa.y, v.x - fa.x);
        uint32_t l1 = pack2h(v.w - fb.y, v.z - fb.x);
        ((uint2*)g_xh)[idx] = make_uint2(h0, h1);
        ((uint2*)g_xl)[idx] = make_uint2(l0, l1);
    } else if (blockIdx.x < 16640) {
        int idx = (blockIdx.x - 16384) * 256 + threadIdx.x;
        float4 v = ((const float4*)W)[idx];
        float a = v.x * 64.f, b = v.y * 64.f, c = v.z * 64.f, d = v.w * 64.f;
        uint32_t h0 = pack2h(b, a), h1 = pack2h(d, c);
        float2 fa = __half22float2(*(__half2*)&h0);
        float2 fb = __half22float2(*(__half2*)&h1);
        uint32_t l0 = pack2h(b - fa.y, a - fa.x);
        uint32_t l1 = pack2h(d - fb.y, c - fb.x);
        ((uint2*)g_wh)[idx] = make_uint2(h0, h1);
        ((uint2*)g_wl)[idx] = make_uint2(l0, l1);
    } else {
        int bx = blockIdx.x - 16640;
        int idx = bx * 256 + threadIdx.x;
        int r = idx >> 8, k2 = idx & 255;
        int e = r >> 4, h = r & 15;
        const float* p = w1 + ((size_t)e * CDIM + 2 * k2) * NH + h;
        float a = p[0] * 64.f, b = p[NH] * 64.f;
        uint32_t hi = pack2h(b, a);
        float2 f = __half22float2(*(__half2*)&hi);
        uint32_t lo = pack2h(b - f.y, a - f.x);
        g_wh[(512 + r) * 256 + k2] = hi;
        g_wl[(512 + r) * 256 + k2] = lo;
        if (bx < 2) {
            int c = bx * 256 + threadIdx.x;
            g_sum[c] = 0.f; g_sumsq[c] = 0.f;
            if (c < NE) g_usage[c] = 0.f;
        }
    }
}

// ---------------- GEMM (round-13 exact): 256 threads, NBUF=3, 2 CTAs/SM ----------------
__global__ __launch_bounds__(256, 2) void k_gemm_mma(const float* __restrict__ bias,
                                                     const float* __restrict__ b1f) {
    extern __shared__ uint32_t sm[];
    const int m0 = blockIdx.x * BM;
    const int n0 = blockIdx.y * BN;
    const bool is_h1 = (blockIdx.y == 4);
    const int tid = threadIdx.x;
    const int lane = tid & 31;
    const int wid = tid >> 5;
    const int wm = (wid & 3) * 32;
    const int wn = (wid >> 2) * 64;
    const int lr = lane >> 2, lc = lane & 3;
    const uint32_t base = smem_u32(sm);

    const int ldrow = tid >> 2, ldch = tid & 3;
    const uint32_t swd = 4u * (uint32_t)SWZ(ldrow, 4 * ldch);
    const uint32_t swd2 = 4u * (uint32_t)SWZ(ldrow + 64, 4 * ldch);
    const uint32_t* pxh = g_xh + (size_t)(m0 + ldrow) * 256 + ldch * 4;
    const uint32_t* pxl = g_xl + (size_t)(m0 + ldrow) * 256 + ldch * 4;
    const uint32_t* pwh = g_wh + (size_t)(n0 + ldrow) * 256 + ldch * 4;
    const uint32_t* pwl = g_wl + (size_t)(n0 + ldrow) * 256 + ldch * 4;
    const int rstep = 64 * 256;

    const int lrow8 = (lane & 7) + 8 * ((lane >> 3) & 1);
    const int kwsel = 4 * (lane >> 4);
    uint32_t aoffs[2][2], boffs[2][4];
#pragma unroll
    for (int h = 0; h < 2; h++) {
        int kw = h * 8 + kwsel;
#pragma unroll
        for (int mt = 0; mt < 2; mt++)
            aoffs[h][mt] = 4u * (uint32_t)SWZ(wm + mt * 16 + lrow8, kw);
#pragma unroll
        for (int g = 0; g < 4; g++)
            boffs[h][g] = 4u * (uint32_t)SWZ(wn + g * 16 + lrow8, kw) + 16384u;
    }

    float acc[2][8][4];
#pragma unroll
    for (int mt = 0; mt < 2; mt++)
#pragma unroll
        for (int nt = 0; nt < 8; nt++)
#pragma unroll
            for (int q = 0; q < 4; q++) acc[mt][nt][q] = 0.f;

#pragma unroll
    for (int s = 0; s < NBUF; s++) {
        uint32_t st = base + s * STAGE_BYTES;
        const uint32_t* sx = pxh + s * 16;
        cpa16(st + swd, sx);
        cpa16(st + swd2, sx + rstep);
        sx = pxl + s * 16;
        cpa16(st + 8192 + swd, sx);
        cpa16(st + 8192 + swd2, sx + rstep);
        sx = pwh + s * 16;
        cpa16(st + 16384 + swd, sx);
        cpa16(st + 16384 + swd2, sx + rstep);
        sx = pwl + s * 16;
        cpa16(st + 24576 + swd, sx);
        cpa16(st + 24576 + swd2, sx + rstep);
        CPA_COMMIT();
    }

    for (int s = 0; s < NSTAGE; s++) {
        if (s <= 13) CPA_WAITN(2);
        else if (s == 14) CPA_WAITN(1);
        else CPA_WAITN(0);
        __syncthreads();

        uint32_t st = base + (s % NBUF) * STAGE_BYTES;
#pragma unroll
        for (int h = 0; h < 2; h++) {
            uint32_t afh[2][4], afl[2][4];
#pragma unroll
            for (int mt = 0; mt < 2; mt++) {
                ldsm4(afh[mt], st + aoffs[h][mt]);
                ldsm4(afl[mt], st + 8192 + aoffs[h][mt]);
            }
#pragma unroll
            for (int g = 0; g < 4; g++) {
                uint32_t bfh[4], bfl[4];
                ldsm4(bfh, st + boffs[h][g]);
                ldsm4(bfl, st + 8192 + boffs[h][g]);
#pragma unroll
                for (int mt = 0; mt < 2; mt++) {
                    mma_f16(acc[mt][g * 2],     afh[mt], bfh[0], bfh[2]);
                    mma_f16(acc[mt][g * 2],     afh[mt], bfl[0], bfl[2]);
                    mma_f16(acc[mt][g * 2],     afl[mt], bfh[0], bfh[2]);
                    mma_f16(acc[mt][g * 2 + 1], afh[mt], bfh[1], bfh[3]);
                    mma_f16(acc[mt][g * 2 + 1], afh[mt], bfl[1], bfl[3]);
                    mma_f16(acc[mt][g * 2 + 1], afl[mt], bfh[1], bfh[3]);
                }
            }
        }
        __syncthreads();
        if (s + 3 < NSTAGE) {
            int sn = s + 3;
            uint32_t st2 = base + (sn % NBUF) * STAGE_BYTES;
            const uint32_t* sx = pxh + sn * 16;
            cpa16(st2 + swd, sx);
            cpa16(st2 + swd2, sx + rstep);
            sx = pxl + sn * 16;
            cpa16(st2 + 8192 + swd, sx);
            cpa16(st2 + 8192 + swd2, sx + rstep);
            sx = pwh + sn * 16;
            cpa16(st2 + 16384 + swd, sx);
            cpa16(st2 + 16384 + swd2, sx + rstep);
            sx = pwl + sn * 16;
            cpa16(st2 + 24576 + swd, sx);
            cpa16(st2 + 24576 + swd2, sx + rstep);
            CPA_COMMIT();
        }
    }

    const float inv = 0.015625f;
    if (!is_h1) {
#pragma unroll
        for (int nt = 0; nt < 8; nt++) {
            int col = n0 + wn + nt * 8 + lc * 2;
            float b0 = __ldg(bias + col), b1 = __ldg(bias + col + 1);
            float s0 = 0.f, s1 = 0.f, q0 = 0.f, q1 = 0.f;
#pragma unroll
            for (int mt = 0; mt < 2; mt++) {
                int row = m0 + wm + mt * 16 + lr;
                float v00 = acc[mt][nt][0] * inv + b0;
                float v01 = acc[mt][nt][1] * inv + b1;
                float v10 = acc[mt][nt][2] * inv + b0;
                float v11 = acc[mt][nt][3] * inv + b1;
                *(float2*)(g_h + (size_t)row * CDIM + col) = make_float2(v00, v01);
                *(float2*)(g_h + (size_t)(row + 8) * CDIM + col) = make_float2(v10, v11);
                s0 += v00 + v10; s1 += v01 + v11;
                q0 = fmaf(v00, v00, q0); q0 = fmaf(v10, v10, q0);
                q1 = fmaf(v01, v01, q1); q1 = fmaf(v11, v11, q1);
            }
#pragma unroll
            for (int off = 4; off < 32; off <<= 1) {
                s0 += __shfl_xor_sync(0xffffffffu, s0, off);
                s1 += __shfl_xor_sync(0xffffffffu, s1, off);
                q0 += __shfl_xor_sync(0xffffffffu, q0, off);
                q1 += __shfl_xor_sync(0xffffffffu, q1, off);
            }
            if (lr == 0) {
                atomicAdd(&g_sum[col], s0);
                atomicAdd(&g_sum[col + 1], s1);
                atomicAdd(&g_sumsq[col], q0);
                atomicAdd(&g_sumsq[col + 1], q1);
            }
        }
    } else {
#pragma unroll
        for (int nt = 0; nt < 8; nt++) {
            int colh = wn + nt * 8 + lc * 2;
            float b0 = __ldg(b1f + colh), b1 = __ldg(b1f + colh + 1);
#pragma unroll
            for (int mt = 0; mt < 2; mt++) {
                int row = m0 + wm + mt * 16 + lr;
                float v00 = fmaxf(acc[mt][nt][0] * inv + b0, 0.f);
                float v01 = fmaxf(acc[mt][nt][1] * inv + b1, 0.f);
                float v10 = fmaxf(acc[mt][nt][2] * inv + b0, 0.f);
                float v11 = fmaxf(acc[mt][nt][3] * inv + b1, 0.f);
                *(float2*)(g_h1 + (size_t)row * 128 + colh) = make_float2(v00, v01);
                *(float2*)(g_h1 + (size_t)(row + 8) * 128 + colh) = make_float2(v10, v11);
            }
        }
    }
}

// ---------------- routing v3: 4 tokens per warp, float2 channels ----------------
__global__ __launch_bounds__(256) void k_route(const float* __restrict__ wg2,
                                               const float* __restrict__ bg2,
                                               const float* __restrict__ gamma,
                                               const float* __restrict__ beta) {
    __shared__ float w2s[NE * CDIM];
    __shared__ float scs[CDIM], shs[CDIM];
    __shared__ float s_us[NE];
    int tid = threadIdx.x;
    for (int i = tid; i < NE * CDIM; i += 256) w2s[i] = wg2[i];
    for (int i = tid; i < CDIM; i += 256) {
        float mu  = g_sum[i] * (1.f / T_TOK);
        float var = g_sumsq[i] * (1.f / T_TOK) - mu * mu;
        float rstd = rsqrtf(var + 1e-5f);
        float sc = gamma[i] * rstd;
        scs[i] = sc;
        shs[i] = beta[i] - sc * mu;
    }
    if (tid < NE) s_us[tid] = 0.f;
    __syncthreads();

    int warp = tid >> 5, lane = tid & 31;
    int t0 = blockIdx.x * 32 + warp * 4;   // 4 tokens per warp
    const float* hp0 = g_h + (size_t)t0 * CDIM;
    float a[4][NE];
#pragma unroll
    for (int tt = 0; tt < 4; tt++)
#pragma unroll
        for (int e = 0; e < NE; e++) a[tt][e] = 0.f;
#pragma unroll
    for (int i = 0; i < 8; i++) {
        int c = 2 * lane + 64 * i;
        float2 sc2 = *(const float2*)(scs + c);
        float2 sh2 = *(const float2*)(shs + c);
        float nx[4], ny[4];
#pragma unroll
        for (int tt = 0; tt < 4; tt++) {
            float2 hv = *(const float2*)(hp0 + (size_t)tt * CDIM + c);
            nx[tt] = fmaxf(fmaf(hv.x, sc2.x, sh2.x), 0.f);
            ny[tt] = fmaxf(fmaf(hv.y, sc2.y, sh2.y), 0.f);
        }
#pragma unroll
        for (int e = 0; e < NE; e++) {
            float2 w = *(const float2*)(w2s + e * CDIM + c);
#pragma unroll
            for (int tt = 0; tt < 4; tt++) {
                a[tt][e] = fmaf(nx[tt], w.x, a[tt][e]);
                a[tt][e] = fmaf(ny[tt], w.y, a[tt][e]);
            }
        }
    }
#pragma unroll
    for (int tt = 0; tt < 4; tt++)
#pragma unroll
        for (int e = 0; e < NE; e++)
#pragma unroll
            for (int off = 16; off > 0; off >>= 1)
                a[tt][e] += __shfl_xor_sync(0xffffffffu, a[tt][e], off);
    if (lane == 0) {
#pragma unroll
        for (int tt = 0; tt < 4; tt++) {
            int t = t0 + tt;
            float lg[NE];
#pragma unroll
            for (int e = 0; e < NE; e++) lg[e] = a[tt][e] + bg2[e];
            int i1 = 0; float v1 = lg[0];
#pragma unroll
            for (int e = 1; e < NE; e++) if (lg[e] > v1) { v1 = lg[e]; i1 = e; }
            int i2 = (i1 == 0) ? 1 : 0; float v2 = lg[i2];
#pragma unroll
            for (int e = 0; e < NE; e++)
                if (e != i1 && lg[e] > v2) { v2 = lg[e]; i2 = e; }
            float ew = expf(v2 - v1);
            float invs = 1.f / (1.f + ew);
            float wa = invs, wb = ew * invs;
            g_te[t * 2] = i1; g_te[t * 2 + 1] = i2;
            g_tw[t * 2] = wa; g_tw[t * 2 + 1] = wb;
            atomicAdd(&s_us[i1], wa);
            atomicAdd(&s_us[i2], wb);
        }
    }
    __syncthreads();
    if (tid < NE) atomicAdd(&g_usage[tid], s_us[tid]);
}

// ---------------- expert v4: phase-2 only ----------------
__global__ __launch_bounds__(256, 2) void k_expert(const float* __restrict__ w2,
                                                   const float* __restrict__ b2) {
    __shared__ float hs[64 * NH];
    __shared__ float wts[256];
    __shared__ int toks[256];
    __shared__ int slots[256];
    __shared__ int s_cnt;

    int e = blockIdx.y;
    int tid = threadIdx.x;
    if (tid == 0) s_cnt = 0;

    float2 w2r[NH];
    const float* w2p = w2 + (size_t)e * NH * CDIM + 2 * tid;
#pragma unroll
    for (int h = 0; h < NH; h++) w2r[h] = *(const float2*)(w2p + h * CDIM);
    float2 b2r = *(const float2*)(b2 + e * CDIM + 2 * tid);
    __syncthreads();

    {
        int t = blockIdx.x * 256 + tid;
        int e1 = g_te[t * 2], e2 = g_te[t * 2 + 1];
        int slot = (e1 == e) ? 0 : ((e2 == e) ? 1 : -1);
        if (slot >= 0) {
            int p = atomicAdd(&s_cnt, 1);
            toks[p] = t;
            slots[p] = slot;
            wts[p] = g_tw[t * 2 + slot];
        }
    }
    __syncthreads();
    int nact = s_cnt;

    for (int bb = 0; bb < nact; bb += 64) {
        int nb = min(64, nact - bb);
        for (int idx = tid; idx < nb * NH; idx += 256) {
            int r = idx >> 4, h = idx & 15;
            hs[idx] = g_h1[(size_t)toks[bb + r] * 128 + e * NH + h];
        }
        __syncthreads();
        int tl = 0;
        for (; tl + 2 <= nb; tl += 2) {
            float4 p0 = *(float4*)(hs + tl * NH);
            float4 p1 = *(float4*)(hs + tl * NH + 4);
            float4 p2 = *(float4*)(hs + tl * NH + 8);
            float4 p3 = *(float4*)(hs + tl * NH + 12);
            float4 q0v = *(float4*)(hs + (tl + 1) * NH);
            float4 q1v = *(float4*)(hs + (tl + 1) * NH + 4);
            float4 q2v = *(float4*)(hs + (tl + 1) * NH + 8);
            float4 q3v = *(float4*)(hs + (tl + 1) * NH + 12);
            float ha[NH] = { p0.x, p0.y, p0.z, p0.w, p1.x, p1.y, p1.z, p1.w,
                             p2.x, p2.y, p2.z, p2.w, p3.x, p3.y, p3.z, p3.w };
            float hb[NH] = { q0v.x, q0v.y, q0v.z, q0v.w, q1v.x, q1v.y, q1v.z, q1v.w,
                             q2v.x, q2v.y, q2v.z, q2v.w, q3v.x, q3v.y, q3v.z, q3v.w };
            float ra0 = b2r.x, ra1 = b2r.y, rb0 = b2r.x, rb1 = b2r.y;
#pragma unroll
            for (int h = 0; h < NH; h++) {
                ra0 = fmaf(ha[h], w2r[h].x, ra0);
                ra1 = fmaf(ha[h], w2r[h].y, ra1);
                rb0 = fmaf(hb[h], w2r[h].x, rb0);
                rb1 = fmaf(hb[h], w2r[h].y, rb1);
            }
            float wa = wts[bb + tl], wb = wts[bb + tl + 1];
            *(float2*)(&g_of2[slots[bb + tl]][toks[bb + tl]][2 * tid])         = make_float2(wa * ra0, wa * ra1);
            *(float2*)(&g_of2[slots[bb + tl + 1]][toks[bb + tl + 1]][2 * tid]) = make_float2(wb * rb0, wb * rb1);
        }
        if (tl < nb) {
            float4 p0 = *(float4*)(hs + tl * NH);
            float4 p1 = *(float4*)(hs + tl * NH + 4);
            float4 p2 = *(float4*)(hs + tl * NH + 8);
            float4 p3 = *(float4*)(hs + tl * NH + 12);
            float ha[NH] = { p0.x, p0.y, p0.z, p0.w, p1.x, p1.y, p1.z, p1.w,
                             p2.x, p2.y, p2.z, p2.w, p3.x, p3.y, p3.z, p3.w };
            float r0 = b2r.x, r1 = b2r.y;
#pragma unroll
            for (int h = 0; h < NH; h++) {
                r0 = fmaf(ha[h], w2r[h].x, r0);
                r1 = fmaf(ha[h], w2r[h].y, r1);
            }
            float wt = wts[bb + tl];
            *(float2*)(&g_of2[slots[bb + tl]][toks[bb + tl]][2 * tid]) = make_float2(wt * r0, wt * r1);
        }
        __syncthreads();
    }
}

// ---------------- combine + transpose ----------------
__global__ void k_transpose(float* __restrict__ out) {
    __shared__ float tile[32][33];
    int b = blockIdx.z;
    int n0 = blockIdx.x * 32, c0 = blockIdx.y * 32;
    int tx = threadIdx.x, ty = threadIdx.y;
#pragma unroll
    for (int i = 0; i < 4; i++) {
        int t = b * 4096 + n0 + ty + i * 8;
        tile[ty + i * 8][tx] = g_of2[0][t][c0 + tx] + g_of2[1][t][c0 + tx];
    }
    __syncthreads();
#pragma unroll
    for (int i = 0; i < 4; i++) {
        int c = c0 + ty + i * 8;
        out[(size_t)(b * CDIM + c) * 4096 + n0 + tx] = tile[tx][ty + i * 8];
    }
}

// ---------------- load-balance loss ----------------
__global__ void k_lb(float* __restrict__ out, int out_size) {
    float lb = 0.f;
    for (int e = 0; e < NE; e++) {
        float u = g_usage[e] * (1.f / T_TOK);
        lb += u * u;
    }
    lb *= (float)NE;
    if (out_size > T_TOK * CDIM) out[T_TOK * CDIM] = lb;
}

// ---------------- launcher ----------------
extern "C" void kernel_launch(void* const* d_in, const int* in_sizes, int n_in,
                              void* d_out, int out_size) {
    const float* x     = (const float*)d_in[0];
    const float* wg1   = (const float*)d_in[1];
    const float* bg1   = (const float*)d_in[2];
    const float* gamma = (const float*)d_in[3];
    const float* beta  = (const float*)d_in[4];
    const float* wg2   = (const float*)d_in[5];
    const float* bg2   = (const float*)d_in[6];
    const float* w1    = (const float*)d_in[7];
    const float* b1    = (const float*)d_in[8];
    const float* w2    = (const float*)d_in[9];
    const float* b2    = (const float*)d_in[10];
    float* out = (float*)d_out;

    k_split<<<16768, 256>>>(x, wg1, w1);

    int gemm_smem = NBUF * STAGE_BYTES;
    cudaFuncSetAttribute(k_gemm_mma, cudaFuncAttributeMaxDynamicSharedMemorySize, gemm_smem);
    k_gemm_mma<<<dim3(T_TOK / BM, NTOT / BN), 256, gemm_smem>>>(bg1, b1);

    k_route<<<1024, 256>>>(wg2, bg2, gamma, beta);

    k_expert<<<dim3(128, NE), 256>>>(w2, b2);

    k_transpose<<<dim3(128, 16, 8), dim3(32, 8)>>>(out);
    k_lb<<<1, 1>>>(out, out_size);
}